// round 3
// baseline (speedup 1.0000x reference)
#include <cuda_runtime.h>
#include <math.h>

#define BB 2
#define SS 2048
#define DD 1024
#define NH 16
#define NKV 4
#define HD 64
#define KVD 256
#define NE 8
#define INTER 512
#define NTOK (BB*SS)
#define EPSF 1.1920929e-7f

// ---------------- scratch (static device globals; no runtime alloc) ----------------
__device__ float g_xbuf[NTOK*DD];
__device__ float g_nbuf[NTOK*DD];
__device__ float g_qlin[NTOK*DD];
__device__ float g_klin[NTOK*KVD];
__device__ float g_vlin[NTOK*KVD];
__device__ float g_qa[BB*NH*SS*HD];
__device__ float g_ka[BB*NKV*SS*HD];
__device__ float g_va[BB*NKV*SS*HD];
__device__ float g_ybuf[NTOK*DD];
__device__ float g_x2[NTOK*DD];
__device__ float g_x3[NTOK*DD];
__device__ float g_mbuf[NTOK*DD];
__device__ float g_gu[NTOK*2*INTER];
__device__ float g_hbuf[NTOK*INTER];
__device__ int   g_cnt[NE];
__device__ int   g_tok[NE*NTOK];

// ---------------- kernel 1: residual mix + rmsnorm ----------------
__global__ void k_mix_norm(const float* __restrict__ x, const float* __restrict__ x0,
                           const float* __restrict__ rm) {
    int t = blockIdx.x, tid = threadIdx.x;
    const float* xr  = x  + (size_t)t*DD;
    const float* x0r = x0 + (size_t)t*DD;
    float v[4]; float ss = 0.f;
#pragma unroll
    for (int r = 0; r < 4; r++) {
        int d = tid + r*256;
        float xm = rm[d]*xr[d] + rm[DD+d]*x0r[d];
        v[r] = xm; ss += xm*xm;
    }
    __shared__ float red[32];
#pragma unroll
    for (int o = 16; o > 0; o >>= 1) ss += __shfl_xor_sync(0xffffffffu, ss, o);
    if ((tid & 31) == 0) red[tid >> 5] = ss;
    __syncthreads();
    if (tid < 32) {
        float s2 = (tid < 8) ? red[tid] : 0.f;
#pragma unroll
        for (int o = 4; o > 0; o >>= 1) s2 += __shfl_xor_sync(0xffffffffu, s2, o);
        if (tid == 0) red[0] = s2;
    }
    __syncthreads();
    float rms = rsqrtf(red[0]/(float)DD + EPSF);
#pragma unroll
    for (int r = 0; r < 4; r++) {
        int d = tid + r*256;
        g_xbuf[(size_t)t*DD + d] = v[r];
        g_nbuf[(size_t)t*DD + d] = v[r]*rms;
    }
}

// ---------------- TN GEMM: C[M,N] = A[M,K] * W[N,K]^T (both K-major) ----------------
// EPI 0: plain store.  EPI 1: C = xres + scale[col]*acc  (proj epilogue)
template<int EPI>
__global__ void __launch_bounds__(256) gemm_tn(const float* __restrict__ A,
                                               const float* __restrict__ W,
                                               float* __restrict__ C, int N, int K,
                                               const float* __restrict__ xres,
                                               const float* __restrict__ scale) {
    __shared__ __align__(16) float As[8][128];
    __shared__ __align__(16) float Bs[8][128];
    int m0 = blockIdx.y*128, n0 = blockIdx.x*128;
    int tid = threadIdx.x;
    int lr = tid >> 1, lk = (tid & 1)*4;
    int ty = tid >> 4, tx = tid & 15;
    float acc[8][8] = {};
    for (int k0 = 0; k0 < K; k0 += 8) {
        float4 a = *(const float4*)(A + (size_t)(m0+lr)*K + k0 + lk);
        float4 b = *(const float4*)(W + (size_t)(n0+lr)*K + k0 + lk);
        As[lk+0][lr]=a.x; As[lk+1][lr]=a.y; As[lk+2][lr]=a.z; As[lk+3][lr]=a.w;
        Bs[lk+0][lr]=b.x; Bs[lk+1][lr]=b.y; Bs[lk+2][lr]=b.z; Bs[lk+3][lr]=b.w;
        __syncthreads();
#pragma unroll
        for (int kk = 0; kk < 8; kk++) {
            float ra[8], rb[8];
#pragma unroll
            for (int i = 0; i < 8; i++) ra[i] = As[kk][ty*8+i];
#pragma unroll
            for (int j = 0; j < 8; j++) rb[j] = Bs[kk][tx*8+j];
#pragma unroll
            for (int i = 0; i < 8; i++)
#pragma unroll
                for (int j = 0; j < 8; j++) acc[i][j] += ra[i]*rb[j];
        }
        __syncthreads();
    }
#pragma unroll
    for (int i = 0; i < 8; i++) {
        size_t row = m0 + ty*8 + i;
#pragma unroll
        for (int j = 0; j < 8; j++) {
            int col = n0 + tx*8 + j;
            if (EPI == 0) C[row*N + col] = acc[i][j];
            else          C[row*N + col] = xres[row*N + col] + scale[col]*acc[i][j];
        }
    }
}

// ---------------- per-head rmsnorm + rope + layout to head-major ----------------
__global__ void k_hnr(const float* __restrict__ qgain) {
    int t = blockIdx.x;
    int job = blockIdx.y*8 + (threadIdx.x >> 5);
    int lane = threadIdx.x & 31;
    int b = t / SS, s = t % SS;
    float fr = (float)s * __expf(-(float)lane * (9.210340371976184f/32.f));
    float sn, cs; sincosf(fr, &sn, &cs);
    if (job < NH) {
        int h = job;
        float v0 = g_qlin[(size_t)t*DD + h*64 + lane];
        float v1 = g_qlin[(size_t)t*DD + h*64 + 32 + lane];
        float ss2 = v0*v0 + v1*v1;
#pragma unroll
        for (int o = 16; o > 0; o >>= 1) ss2 += __shfl_xor_sync(0xffffffffu, ss2, o);
        float r = rsqrtf(ss2/64.f + EPSF);
        v0 *= r; v1 *= r;
        float g = qgain[h];
        float o0 = (v0*cs + v1*sn)*g;
        float o1 = (-v0*sn + v1*cs)*g;
        size_t base = (((size_t)b*NH + h)*SS + s)*HD;
        g_qa[base + lane] = o0; g_qa[base + 32 + lane] = o1;
    } else if (job < NH + NKV) {
        int h = job - NH;
        float v0 = g_klin[(size_t)t*KVD + h*64 + lane];
        float v1 = g_klin[(size_t)t*KVD + h*64 + 32 + lane];
        float ss2 = v0*v0 + v1*v1;
#pragma unroll
        for (int o = 16; o > 0; o >>= 1) ss2 += __shfl_xor_sync(0xffffffffu, ss2, o);
        float r = rsqrtf(ss2/64.f + EPSF);
        v0 *= r; v1 *= r;
        float o0 = v0*cs + v1*sn;
        float o1 = -v0*sn + v1*cs;
        size_t base = (((size_t)b*NKV + h)*SS + s)*HD;
        g_ka[base + lane] = o0; g_ka[base + 32 + lane] = o1;
    } else {
        int h = job - NH - NKV;
        size_t base = (((size_t)b*NKV + h)*SS + s)*HD;
        g_va[base + lane]      = g_vlin[(size_t)t*KVD + h*64 + lane];
        g_va[base + 32 + lane] = g_vlin[(size_t)t*KVD + h*64 + 32 + lane];
    }
}

// ---------------- causal flash attention, HD=64, 128 q-rows/block ----------------
__global__ void __launch_bounds__(128) k_flash() {
    __shared__ __align__(16) float Ks[64][64];
    __shared__ __align__(16) float Vs[64][64];
    int bh = blockIdx.y;
    int b = bh / NH, h = bh % NH, kh = h / (NH/NKV);
    int row = blockIdx.x*128 + threadIdx.x;
    const float* qp    = g_qa + (((size_t)b*NH + h)*SS + row)*HD;
    const float* kbase = g_ka + (((size_t)b*NKV + kh)*SS)*HD;
    const float* vbase = g_va + (((size_t)b*NKV + kh)*SS)*HD;
    float q[64];
#pragma unroll
    for (int d = 0; d < 64; d++) q[d] = qp[d];
    float o[64] = {};
    float m = -1e30f, l = 0.f;
    int nkt = 2*(blockIdx.x + 1);
    for (int kt = 0; kt < nkt; kt++) {
        __syncthreads();
        for (int i = threadIdx.x; i < 64*16; i += 128) {
            int j = i >> 4, d4 = i & 15;
            ((float4*)&Ks[j][0])[d4] = ((const float4*)(kbase + (size_t)(kt*64 + j)*64))[d4];
            ((float4*)&Vs[j][0])[d4] = ((const float4*)(vbase + (size_t)(kt*64 + j)*64))[d4];
        }
        __syncthreads();
        int kb = kt*64;
        for (int jc = 0; jc < 64; jc += 16) {
            if (kb + jc > row) break;
            float sc[16]; float cmax = -1e30f;
#pragma unroll
            for (int jj = 0; jj < 16; jj++) {
                int j = jc + jj;
                float dot = 0.f;
                const float4* kr = (const float4*)&Ks[j][0];
#pragma unroll
                for (int d4 = 0; d4 < 16; d4++) {
                    float4 kk = kr[d4];
                    dot += q[4*d4+0]*kk.x + q[4*d4+1]*kk.y + q[4*d4+2]*kk.z + q[4*d4+3]*kk.w;
                }
                float sv = (kb + j <= row) ? dot*0.125f : -1e30f;
                sc[jj] = sv; cmax = fmaxf(cmax, sv);
            }
            float mn = fmaxf(m, cmax);
            float corr = __expf(m - mn);
            l *= corr;
#pragma unroll
            for (int d = 0; d < 64; d++) o[d] *= corr;
            m = mn;
#pragma unroll
            for (int jj = 0; jj < 16; jj++) {
                float p = __expf(sc[jj] - m);
                l += p;
                const float4* vr = (const float4*)&Vs[jc+jj][0];
#pragma unroll
                for (int d4 = 0; d4 < 16; d4++) {
                    float4 vv = vr[d4];
                    o[4*d4+0] += p*vv.x; o[4*d4+1] += p*vv.y;
                    o[4*d4+2] += p*vv.z; o[4*d4+3] += p*vv.w;
                }
            }
        }
    }
    float inv = 1.f/l;
    size_t ob = ((size_t)(b*SS + row))*DD + h*64;
#pragma unroll
    for (int d = 0; d < 64; d++) g_ybuf[ob + d] = o[d]*inv;
}

// ---------------- zero expert counters ----------------
__global__ void k_zero() { if (threadIdx.x < NE) g_cnt[threadIdx.x] = 0; }

// ---------------- velocity + second rmsnorm + expert bucketing ----------------
__global__ void k_vel(const float* __restrict__ vel, const float* __restrict__ mu,
                      const int* __restrict__ eids, float* __restrict__ out) {
    int t = blockIdx.x, tid = threadIdx.x;
    float xv[4]; float ss = 0.f;
#pragma unroll
    for (int r = 0; r < 4; r++) {
        int d = tid + r*256;
        size_t idx = (size_t)t*DD + d;
        float x2 = g_x2[idx];
        float mc = fminf(fmaxf(mu[d], 0.5f), 1.5f);
        float v = fminf(fmaxf(0.95f*vel[idx] - 0.3f*(x2 - mc), -3.f), 3.f);
        out[(size_t)NTOK*DD + idx] = v;
        float x3 = x2 + 0.01f*v;
        xv[r] = x3; ss += x3*x3;
        g_x3[idx] = x3;
    }
    __shared__ float red[32];
#pragma unroll
    for (int o = 16; o > 0; o >>= 1) ss += __shfl_xor_sync(0xffffffffu, ss, o);
    if ((tid & 31) == 0) red[tid >> 5] = ss;
    __syncthreads();
    if (tid < 32) {
        float s2 = (tid < 8) ? red[tid] : 0.f;
#pragma unroll
        for (int o = 4; o > 0; o >>= 1) s2 += __shfl_xor_sync(0xffffffffu, s2, o);
        if (tid == 0) red[0] = s2;
    }
    __syncthreads();
    float rms = rsqrtf(red[0]/(float)DD + EPSF);
#pragma unroll
    for (int r = 0; r < 4; r++) {
        int d = tid + r*256;
        g_mbuf[(size_t)t*DD + d] = xv[r]*rms;
    }
    if (tid == 0) {
        int e = eids[t];
        int p = atomicAdd(&g_cnt[e], 1);
        g_tok[e*NTOK + p] = t;
    }
}

// ---------------- gathered NN GEMM per expert: C[rows,N] = A[rows,K] * W[e][K,N] ----
// EPI 0: store to Cdst (gate_up).  EPI 1: out = x3 + scale[col]*acc (down, final out)
template<int EPI>
__global__ void __launch_bounds__(256) gemm_nn_g(const float* __restrict__ A,
                                                 const float* __restrict__ Wbase,
                                                 int N, int K,
                                                 float* __restrict__ Cdst,
                                                 const float* __restrict__ scale,
                                                 float* __restrict__ out) {
    int e = blockIdx.z;
    int cnt = g_cnt[e];
    int m0 = blockIdx.y*128;
    if (m0 >= cnt) return;
    int n0 = blockIdx.x*128;
    const float* W = Wbase + (size_t)e*K*N;
    __shared__ __align__(16) float As[8][128];
    __shared__ __align__(16) float Bs[8][128];
    __shared__ int rows[128];
    int tid = threadIdx.x;
    if (tid < 128) {
        int mi = m0 + tid;
        rows[tid] = (mi < cnt) ? g_tok[e*NTOK + mi] : 0;
    }
    __syncthreads();
    int lr = tid >> 1, lk = (tid & 1)*4;
    int bk = tid >> 5, bn = (tid & 31)*4;
    int ty = tid >> 4, tx = tid & 15;
    float acc[8][8] = {};
    for (int k0 = 0; k0 < K; k0 += 8) {
        float4 a = *(const float4*)(A + (size_t)rows[lr]*K + k0 + lk);
        float4 b = *(const float4*)(W + (size_t)(k0 + bk)*N + n0 + bn);
        As[lk+0][lr]=a.x; As[lk+1][lr]=a.y; As[lk+2][lr]=a.z; As[lk+3][lr]=a.w;
        *(float4*)&Bs[bk][bn] = b;
        __syncthreads();
#pragma unroll
        for (int kk = 0; kk < 8; kk++) {
            float ra[8], rb[8];
#pragma unroll
            for (int i = 0; i < 8; i++) ra[i] = As[kk][ty*8+i];
#pragma unroll
            for (int j = 0; j < 8; j++) rb[j] = Bs[kk][tx*8+j];
#pragma unroll
            for (int i = 0; i < 8; i++)
#pragma unroll
                for (int j = 0; j < 8; j++) acc[i][j] += ra[i]*rb[j];
        }
        __syncthreads();
    }
#pragma unroll
    for (int i = 0; i < 8; i++) {
        int mi = m0 + ty*8 + i;
        if (mi >= cnt) continue;
        size_t row = rows[ty*8 + i];
#pragma unroll
        for (int j = 0; j < 8; j++) {
            int col = n0 + tx*8 + j;
            if (EPI == 0) Cdst[row*(size_t)N + col] = acc[i][j];
            else out[row*(size_t)DD + col] = g_x3[row*(size_t)DD + col] + scale[col]*acc[i][j];
        }
    }
}

// ---------------- silu(g)*u ----------------
__global__ void k_silu() {
    int idx = blockIdx.x*256 + threadIdx.x;
    int t = idx >> 9, i = idx & 511;
    float g = g_gu[(size_t)t*1024 + i];
    float u = g_gu[(size_t)t*1024 + 512 + i];
    g_hbuf[(size_t)t*512 + i] = g/(1.f + __expf(-g))*u;
}

// ---------------- launch ----------------
extern "C" void kernel_launch(void* const* d_in, const int* in_sizes, int n_in,
                              void* d_out, int out_size) {
    const float* x        = (const float*)d_in[0];
    const float* x0       = (const float*)d_in[1];
    const float* vel      = (const float*)d_in[2];
    const float* resid    = (const float*)d_in[3];
    const float* attn_sc  = (const float*)d_in[4];
    const float* mlp_sc   = (const float*)d_in[5];
    const float* cq_w     = (const float*)d_in[6];
    const float* ck_w     = (const float*)d_in[7];
    const float* cv_w     = (const float*)d_in[8];
    const float* proj_w   = (const float*)d_in[9];
    const float* q_gain   = (const float*)d_in[10];
    const float* mu       = (const float*)d_in[11];
    const float* gate_up  = (const float*)d_in[12];
    const float* down     = (const float*)d_in[13];
    const int*   eids     = (const int*)d_in[14];
    float* out = (float*)d_out;

    float *p_nbuf, *p_qlin, *p_klin, *p_vlin, *p_ybuf, *p_x2, *p_gu, *p_h, *p_m;
    cudaGetSymbolAddress((void**)&p_nbuf, g_nbuf);
    cudaGetSymbolAddress((void**)&p_qlin, g_qlin);
    cudaGetSymbolAddress((void**)&p_klin, g_klin);
    cudaGetSymbolAddress((void**)&p_vlin, g_vlin);
    cudaGetSymbolAddress((void**)&p_ybuf, g_ybuf);
    cudaGetSymbolAddress((void**)&p_x2,   g_x2);
    cudaGetSymbolAddress((void**)&p_gu,   g_gu);
    cudaGetSymbolAddress((void**)&p_h,    g_hbuf);
    cudaGetSymbolAddress((void**)&p_m,    g_mbuf);
    float *p_xbuf;
    cudaGetSymbolAddress((void**)&p_xbuf, g_xbuf);

    k_mix_norm<<<NTOK, 256>>>(x, x0, resid);

    gemm_tn<0><<<dim3(DD/128,  NTOK/128), 256>>>(p_nbuf, cq_w, p_qlin, DD,  DD, nullptr, nullptr);
    gemm_tn<0><<<dim3(KVD/128, NTOK/128), 256>>>(p_nbuf, ck_w, p_klin, KVD, DD, nullptr, nullptr);
    gemm_tn<0><<<dim3(KVD/128, NTOK/128), 256>>>(p_nbuf, cv_w, p_vlin, KVD, DD, nullptr, nullptr);

    k_hnr<<<dim3(NTOK, 3), 256>>>(q_gain);

    k_flash<<<dim3(SS/128, BB*NH), 128>>>();

    gemm_tn<1><<<dim3(DD/128, NTOK/128), 256>>>(p_ybuf, proj_w, p_x2, DD, DD, p_xbuf, attn_sc);

    k_zero<<<1, 32>>>();
    k_vel<<<NTOK, 256>>>(vel, mu, eids, out);

    gemm_nn_g<0><<<dim3(1024/128, NTOK/128, NE), 256>>>(p_m, gate_up, 1024, DD, p_gu, nullptr, nullptr);
    k_silu<<<(NTOK*INTER)/256, 256>>>();
    gemm_nn_g<1><<<dim3(DD/128, NTOK/128, NE), 256>>>(p_h, down, DD, INTER, nullptr, mlp_sc, out);
}

// round 8
// speedup vs baseline: 2.9566x; 2.9566x over previous
#include <cuda_runtime.h>
#include <math.h>
#include <stdint.h>

#define BB 2
#define SS 2048
#define DD 1024
#define NH 16
#define NKV 4
#define HD 64
#define KVD 256
#define NE 8
#define INTER 512
#define NTOK (BB*SS)
#define EPSF 1.1920929e-7f

// ---------------- scratch (static device globals; no runtime alloc) ----------------
__device__ float g_xbuf[NTOK*DD];
__device__ float g_nbuf[NTOK*DD];
__device__ float g_qlin[NTOK*DD];
__device__ float g_klin[NTOK*KVD];
__device__ float g_vlin[NTOK*KVD];
__device__ float g_qa[BB*NH*SS*HD];
__device__ float g_ka[BB*NKV*SS*HD];
__device__ float g_va[BB*NKV*SS*HD];
__device__ float g_ybuf[NTOK*DD];
__device__ float g_x2[NTOK*DD];
__device__ float g_x3[NTOK*DD];
__device__ float g_mbuf[NTOK*DD];
__device__ float g_gu[NTOK*2*INTER];
__device__ float g_hbuf[NTOK*INTER];
__device__ int   g_cnt[NE];
__device__ int   g_tok[NE*NTOK];

// ---------------- tf32 helpers ----------------
__device__ __forceinline__ uint32_t f2tf(float f) {
    uint32_t u; asm("cvt.rna.tf32.f32 %0, %1;" : "=r"(u) : "f"(f)); return u;
}
__device__ __forceinline__ void mma_tf32(float& c0, float& c1, float& c2, float& c3,
                                         uint32_t a0, uint32_t a1, uint32_t a2, uint32_t a3,
                                         uint32_t b0, uint32_t b1) {
    asm volatile("mma.sync.aligned.m16n8k8.row.col.f32.tf32.tf32.f32 "
                 "{%0,%1,%2,%3}, {%4,%5,%6,%7}, {%8,%9}, {%0,%1,%2,%3};\n"
                 : "+f"(c0), "+f"(c1), "+f"(c2), "+f"(c3)
                 : "r"(a0), "r"(a1), "r"(a2), "r"(a3), "r"(b0), "r"(b1));
}

// ---------------- kernel 1: residual mix + rmsnorm ----------------
__global__ void k_mix_norm(const float* __restrict__ x, const float* __restrict__ x0,
                           const float* __restrict__ rm) {
    int t = blockIdx.x, tid = threadIdx.x;
    const float* xr  = x  + (size_t)t*DD;
    const float* x0r = x0 + (size_t)t*DD;
    float v[4]; float ss = 0.f;
#pragma unroll
    for (int r = 0; r < 4; r++) {
        int d = tid + r*256;
        float xm = rm[d]*xr[d] + rm[DD+d]*x0r[d];
        v[r] = xm; ss += xm*xm;
    }
    __shared__ float red[32];
#pragma unroll
    for (int o = 16; o > 0; o >>= 1) ss += __shfl_xor_sync(0xffffffffu, ss, o);
    if ((tid & 31) == 0) red[tid >> 5] = ss;
    __syncthreads();
    if (tid < 32) {
        float s2 = (tid < 8) ? red[tid] : 0.f;
#pragma unroll
        for (int o = 4; o > 0; o >>= 1) s2 += __shfl_xor_sync(0xffffffffu, s2, o);
        if (tid == 0) red[0] = s2;
    }
    __syncthreads();
    float rms = rsqrtf(red[0]/(float)DD + EPSF);
#pragma unroll
    for (int r = 0; r < 4; r++) {
        int d = tid + r*256;
        g_xbuf[(size_t)t*DD + d] = v[r];
        g_nbuf[(size_t)t*DD + d] = v[r]*rms;
    }
}

// ---------------- tf32 MMA TN GEMM: C[M,N] = A[M,K] * W[N,K]^T ----------------
template<int EPI>
__global__ void __launch_bounds__(256) gemm_mma_tn(const float* __restrict__ A,
                                                   const float* __restrict__ W,
                                                   const float* __restrict__ W1,
                                                   float* __restrict__ C,
                                                   float* __restrict__ C1,
                                                   int N, int K,
                                                   const float* __restrict__ xres,
                                                   const float* __restrict__ scale) {
    if (blockIdx.z == 1) { W = W1; C = C1; }
    __shared__ uint32_t As[128][32];
    __shared__ uint32_t Bs[128][32];
    int m0 = blockIdx.y*128, n0 = blockIdx.x*128;
    int tid = threadIdx.x;
    int wid = tid >> 5, lane = tid & 31;
    int wm = wid >> 2, wn = wid & 3;
    int q = lane >> 2, c = lane & 3;
    float acc[4][4][4] = {};
    for (int k0 = 0; k0 < K; k0 += 32) {
#pragma unroll
        for (int i = 0; i < 4; i++) {
            int idx = i*256 + tid;
            int r = idx >> 3, kq = idx & 7;
            int kqs = kq ^ (r & 7);
            float4 av = *(const float4*)(A + (size_t)(m0+r)*K + k0 + kq*4);
            uint32_t* da = &As[r][kqs*4];
            da[0]=f2tf(av.x); da[1]=f2tf(av.y); da[2]=f2tf(av.z); da[3]=f2tf(av.w);
            float4 bv = *(const float4*)(W + (size_t)(n0+r)*K + k0 + kq*4);
            uint32_t* db = &Bs[r][kqs*4];
            db[0]=f2tf(bv.x); db[1]=f2tf(bv.y); db[2]=f2tf(bv.z); db[3]=f2tf(bv.w);
        }
        __syncthreads();
#pragma unroll
        for (int ks = 0; ks < 4; ks++) {
            int kb = ks*8;
            int g0 = kb >> 2, g1 = g0 + 1;
            int ki0 = c + 4*(g0 ^ q);
            int ki1 = c + 4*(g1 ^ q);
            uint32_t af[4][4];
#pragma unroll
            for (int mt = 0; mt < 4; mt++) {
                int rb = wm*64 + mt*16;
                af[mt][0] = As[rb + q][ki0];
                af[mt][1] = As[rb + 8 + q][ki0];
                af[mt][2] = As[rb + q][ki1];
                af[mt][3] = As[rb + 8 + q][ki1];
            }
#pragma unroll
            for (int nt = 0; nt < 4; nt++) {
                int col = wn*32 + nt*8 + q;
                uint32_t b0 = Bs[col][ki0];
                uint32_t b1 = Bs[col][ki1];
#pragma unroll
                for (int mt = 0; mt < 4; mt++)
                    mma_tf32(acc[mt][nt][0], acc[mt][nt][1], acc[mt][nt][2], acc[mt][nt][3],
                             af[mt][0], af[mt][1], af[mt][2], af[mt][3], b0, b1);
            }
        }
        __syncthreads();
    }
#pragma unroll
    for (int mt = 0; mt < 4; mt++) {
        int row0 = m0 + wm*64 + mt*16 + q;
#pragma unroll
        for (int nt = 0; nt < 4; nt++) {
            int col = n0 + wn*32 + nt*8 + 2*c;
            float2 v01, v23;
            if (EPI == 0) {
                v01 = make_float2(acc[mt][nt][0], acc[mt][nt][1]);
                v23 = make_float2(acc[mt][nt][2], acc[mt][nt][3]);
            } else {
                float s0 = scale[col], s1 = scale[col+1];
                size_t i0 = (size_t)row0*N + col;
                size_t i1 = (size_t)(row0+8)*N + col;
                v01 = make_float2(xres[i0] + s0*acc[mt][nt][0], xres[i0+1] + s1*acc[mt][nt][1]);
                v23 = make_float2(xres[i1] + s0*acc[mt][nt][2], xres[i1+1] + s1*acc[mt][nt][3]);
            }
            *(float2*)(C + (size_t)row0*N + col)     = v01;
            *(float2*)(C + (size_t)(row0+8)*N + col) = v23;
        }
    }
}

// ---------------- tf32 MMA gathered NN GEMM per expert ----------------
template<int EPI>
__global__ void __launch_bounds__(256) gemm_mma_nn(const float* __restrict__ A,
                                                   const float* __restrict__ Wbase,
                                                   int N, int K,
                                                   float* __restrict__ Cdst,
                                                   const float* __restrict__ scale,
                                                   float* __restrict__ out) {
    int e = blockIdx.z;
    int cnt = g_cnt[e];
    int m0 = blockIdx.y*128;
    if (m0 >= cnt) return;
    int n0 = blockIdx.x*128;
    const float* W = Wbase + (size_t)e*K*N;
    __shared__ uint32_t As[128][32];
    __shared__ uint32_t Bs[32][136];
    __shared__ int rows[128];
    int tid = threadIdx.x;
    if (tid < 128) {
        int mi = m0 + tid;
        rows[tid] = (mi < cnt) ? g_tok[e*NTOK + mi] : 0;
    }
    __syncthreads();
    int wid = tid >> 5, lane = tid & 31;
    int wm = wid >> 2, wn = wid & 3;
    int q = lane >> 2, c = lane & 3;
    float acc[4][4][4] = {};
    for (int k0 = 0; k0 < K; k0 += 32) {
#pragma unroll
        for (int i = 0; i < 4; i++) {
            int idx = i*256 + tid;
            int r = idx >> 3, kq = idx & 7;
            int kqs = kq ^ (r & 7);
            float4 av = *(const float4*)(A + (size_t)rows[r]*K + k0 + kq*4);
            uint32_t* da = &As[r][kqs*4];
            da[0]=f2tf(av.x); da[1]=f2tf(av.y); da[2]=f2tf(av.z); da[3]=f2tf(av.w);
            int kk = idx >> 5, nq = idx & 31;
            float4 bv = *(const float4*)(W + (size_t)(k0+kk)*N + n0 + nq*4);
            uint32_t* db = &Bs[kk][nq*4];
            db[0]=f2tf(bv.x); db[1]=f2tf(bv.y); db[2]=f2tf(bv.z); db[3]=f2tf(bv.w);
        }
        __syncthreads();
#pragma unroll
        for (int ks = 0; ks < 4; ks++) {
            int kb = ks*8;
            int g0 = kb >> 2, g1 = g0 + 1;
            int ki0 = c + 4*(g0 ^ q);
            int ki1 = c + 4*(g1 ^ q);
            uint32_t af[4][4];
#pragma unroll
            for (int mt = 0; mt < 4; mt++) {
                int rb = wm*64 + mt*16;
                af[mt][0] = As[rb + q][ki0];
                af[mt][1] = As[rb + 8 + q][ki0];
                af[mt][2] = As[rb + q][ki1];
                af[mt][3] = As[rb + 8 + q][ki1];
            }
#pragma unroll
            for (int nt = 0; nt < 4; nt++) {
                int col = wn*32 + nt*8 + q;
                uint32_t b0 = Bs[kb + c][col];
                uint32_t b1 = Bs[kb + 4 + c][col];
#pragma unroll
                for (int mt = 0; mt < 4; mt++)
                    mma_tf32(acc[mt][nt][0], acc[mt][nt][1], acc[mt][nt][2], acc[mt][nt][3],
                             af[mt][0], af[mt][1], af[mt][2], af[mt][3], b0, b1);
            }
        }
        __syncthreads();
    }
#pragma unroll
    for (int mt = 0; mt < 4; mt++) {
        int lr0 = wm*64 + mt*16 + q;
#pragma unroll
        for (int half = 0; half < 2; half++) {
            int lr = lr0 + half*8;
            if (m0 + lr >= cnt) continue;
            size_t tok = rows[lr];
#pragma unroll
            for (int nt = 0; nt < 4; nt++) {
                int col = n0 + wn*32 + nt*8 + 2*c;
                float a0 = acc[mt][nt][half*2 + 0];
                float a1 = acc[mt][nt][half*2 + 1];
                if (EPI == 0) {
                    *(float2*)(Cdst + tok*(size_t)N + col) = make_float2(a0, a1);
                } else {
                    size_t i0 = tok*(size_t)DD + col;
                    *(float2*)(out + i0) = make_float2(g_x3[i0] + scale[col]*a0,
                                                       g_x3[i0+1] + scale[col+1]*a1);
                }
            }
        }
    }
}

// ---------------- per-head rmsnorm + rope + layout to head-major ----------------
__global__ void k_hnr(const float* __restrict__ qgain) {
    int t = blockIdx.x;
    int job = blockIdx.y*8 + (threadIdx.x >> 5);
    int lane = threadIdx.x & 31;
    int b = t / SS, s = t % SS;
    float fr = (float)s * __expf(-(float)lane * (9.210340371976184f/32.f));
    float sn, cs; sincosf(fr, &sn, &cs);
    if (job < NH) {
        int h = job;
        float v0 = g_qlin[(size_t)t*DD + h*64 + lane];
        float v1 = g_qlin[(size_t)t*DD + h*64 + 32 + lane];
        float ss2 = v0*v0 + v1*v1;
#pragma unroll
        for (int o = 16; o > 0; o >>= 1) ss2 += __shfl_xor_sync(0xffffffffu, ss2, o);
        float r = rsqrtf(ss2/64.f + EPSF);
        v0 *= r; v1 *= r;
        float g = qgain[h];
        float o0 = (v0*cs + v1*sn)*g;
        float o1 = (-v0*sn + v1*cs)*g;
        size_t base = (((size_t)b*NH + h)*SS + s)*HD;
        g_qa[base + lane] = o0; g_qa[base + 32 + lane] = o1;
    } else if (job < NH + NKV) {
        int h = job - NH;
        float v0 = g_klin[(size_t)t*KVD + h*64 + lane];
        float v1 = g_klin[(size_t)t*KVD + h*64 + 32 + lane];
        float ss2 = v0*v0 + v1*v1;
#pragma unroll
        for (int o = 16; o > 0; o >>= 1) ss2 += __shfl_xor_sync(0xffffffffu, ss2, o);
        float r = rsqrtf(ss2/64.f + EPSF);
        v0 *= r; v1 *= r;
        float o0 = v0*cs + v1*sn;
        float o1 = -v0*sn + v1*cs;
        size_t base = (((size_t)b*NKV + h)*SS + s)*HD;
        g_ka[base + lane] = o0; g_ka[base + 32 + lane] = o1;
    } else {
        int h = job - NH - NKV;
        size_t base = (((size_t)b*NKV + h)*SS + s)*HD;
        g_va[base + lane]      = g_vlin[(size_t)t*KVD + h*64 + lane];
        g_va[base + 32 + lane] = g_vlin[(size_t)t*KVD + h*64 + 32 + lane];
    }
}

// ---------------- tf32 MMA causal flash attention ----------------
// 8 warps/CTA, warp w owns 16 q-rows; K/V tiles 64x64 in smem (stride 68).
// QK^T and PV on m16n8k8; online softmax on C-fragments; P remapped to
// A-fragments via intra-quad shuffles (no smem round trip).
__global__ void __launch_bounds__(256) k_flash_mma() {
    __shared__ float Ks[64][68];
    __shared__ float Vs[64][68];
    int bh = blockIdx.y;
    int b = bh / NH, h = bh % NH, kh = h / (NH/NKV);
    int w = threadIdx.x >> 5, lane = threadIdx.x & 31;
    int q = lane >> 2, c = lane & 3;
    int rowbase = blockIdx.x*128 + w*16;
    const float* kbasep = g_ka + ((size_t)(b*NKV + kh)*SS)*HD;
    const float* vbasep = g_va + ((size_t)(b*NKV + kh)*SS)*HD;

    // Q fragments (pre-scaled by 1/sqrt(64))
    uint32_t qf[8][4];
    {
        const float* qp = g_qa + (((size_t)b*NH + h)*SS + rowbase)*HD;
#pragma unroll
        for (int ks = 0; ks < 8; ks++) {
            qf[ks][0] = f2tf(0.125f*qp[(size_t)q*HD     + ks*8 + c]);
            qf[ks][1] = f2tf(0.125f*qp[(size_t)(q+8)*HD + ks*8 + c]);
            qf[ks][2] = f2tf(0.125f*qp[(size_t)q*HD     + ks*8 + c + 4]);
            qf[ks][3] = f2tf(0.125f*qp[(size_t)(q+8)*HD + ks*8 + c + 4]);
        }
    }
    float o[8][4] = {};
    float m_a = -1e30f, m_b = -1e30f, l_a = 0.f, l_b = 0.f;
    unsigned src0 = (lane & ~3u) | (unsigned)(c >> 1);
    unsigned src1 = src0 | 2u;
    int ra = rowbase + q, rb = ra + 8;
    int nkt = 2*blockIdx.x + 2;

    for (int kt = 0; kt < nkt; kt++) {
        int kb = kt*64;
        __syncthreads();
        for (int i = threadIdx.x; i < 64*16; i += 256) {
            int r = i >> 4, c4 = (i & 15)*4;
            float4 kv = *(const float4*)(kbasep + (size_t)(kb + r)*HD + c4);
            float4 vv = *(const float4*)(vbasep + (size_t)(kb + r)*HD + c4);
            Ks[r][c4+0] = __uint_as_float(f2tf(kv.x));
            Ks[r][c4+1] = __uint_as_float(f2tf(kv.y));
            Ks[r][c4+2] = __uint_as_float(f2tf(kv.z));
            Ks[r][c4+3] = __uint_as_float(f2tf(kv.w));
            Vs[r][c4+0] = __uint_as_float(f2tf(vv.x));
            Vs[r][c4+1] = __uint_as_float(f2tf(vv.y));
            Vs[r][c4+2] = __uint_as_float(f2tf(vv.z));
            Vs[r][c4+3] = __uint_as_float(f2tf(vv.w));
        }
        __syncthreads();
        if (kb > rowbase + 15) continue;    // no keys <= any row of this warp

        // ---- QK^T: scores s[nb][0..3] ----
        float s[8][4];
#pragma unroll
        for (int nb = 0; nb < 8; nb++) { s[nb][0]=0.f; s[nb][1]=0.f; s[nb][2]=0.f; s[nb][3]=0.f; }
#pragma unroll
        for (int ks = 0; ks < 8; ks++) {
#pragma unroll
            for (int nb = 0; nb < 8; nb++) {
                uint32_t b0 = __float_as_uint(Ks[nb*8 + q][ks*8 + c]);
                uint32_t b1 = __float_as_uint(Ks[nb*8 + q][ks*8 + c + 4]);
                mma_tf32(s[nb][0], s[nb][1], s[nb][2], s[nb][3],
                         qf[ks][0], qf[ks][1], qf[ks][2], qf[ks][3], b0, b1);
            }
        }
        // ---- causal mask (diagonal tiles only) ----
        if (kb + 63 > rowbase) {
#pragma unroll
            for (int nb = 0; nb < 8; nb++) {
                int col0 = kb + nb*8 + 2*c, col1 = col0 + 1;
                if (col0 > ra) s[nb][0] = -1e30f;
                if (col1 > ra) s[nb][1] = -1e30f;
                if (col0 > rb) s[nb][2] = -1e30f;
                if (col1 > rb) s[nb][3] = -1e30f;
            }
        }
        // ---- online softmax ----
        float mx_a = -1e30f, mx_b = -1e30f;
#pragma unroll
        for (int nb = 0; nb < 8; nb++) {
            mx_a = fmaxf(mx_a, fmaxf(s[nb][0], s[nb][1]));
            mx_b = fmaxf(mx_b, fmaxf(s[nb][2], s[nb][3]));
        }
        mx_a = fmaxf(mx_a, __shfl_xor_sync(0xffffffffu, mx_a, 1));
        mx_a = fmaxf(mx_a, __shfl_xor_sync(0xffffffffu, mx_a, 2));
        mx_b = fmaxf(mx_b, __shfl_xor_sync(0xffffffffu, mx_b, 1));
        mx_b = fmaxf(mx_b, __shfl_xor_sync(0xffffffffu, mx_b, 2));
        float mn_a = fmaxf(m_a, mx_a), mn_b = fmaxf(m_b, mx_b);
        float corr_a = __expf(m_a - mn_a), corr_b = __expf(m_b - mn_b);
        m_a = mn_a; m_b = mn_b;
        float sum_a = 0.f, sum_b = 0.f;
#pragma unroll
        for (int nb = 0; nb < 8; nb++) {
            s[nb][0] = __expf(s[nb][0] - m_a);
            s[nb][1] = __expf(s[nb][1] - m_a);
            s[nb][2] = __expf(s[nb][2] - m_b);
            s[nb][3] = __expf(s[nb][3] - m_b);
            sum_a += s[nb][0] + s[nb][1];
            sum_b += s[nb][2] + s[nb][3];
            o[nb][0] *= corr_a; o[nb][1] *= corr_a;
            o[nb][2] *= corr_b; o[nb][3] *= corr_b;
        }
        sum_a += __shfl_xor_sync(0xffffffffu, sum_a, 1);
        sum_a += __shfl_xor_sync(0xffffffffu, sum_a, 2);
        sum_b += __shfl_xor_sync(0xffffffffu, sum_b, 1);
        sum_b += __shfl_xor_sync(0xffffffffu, sum_b, 2);
        l_a = l_a*corr_a + sum_a;
        l_b = l_b*corr_b + sum_b;
        // ---- PV: remap P C-frags -> A-frags via shuffles, accumulate o ----
#pragma unroll
        for (int ks = 0; ks < 8; ks++) {
            float t0 = __shfl_sync(0xffffffffu, s[ks][0], src0);
            float t1 = __shfl_sync(0xffffffffu, s[ks][1], src0);
            float t2 = __shfl_sync(0xffffffffu, s[ks][2], src0);
            float t3 = __shfl_sync(0xffffffffu, s[ks][3], src0);
            float u0 = __shfl_sync(0xffffffffu, s[ks][0], src1);
            float u1 = __shfl_sync(0xffffffffu, s[ks][1], src1);
            float u2 = __shfl_sync(0xffffffffu, s[ks][2], src1);
            float u3 = __shfl_sync(0xffffffffu, s[ks][3], src1);
            uint32_t a0 = f2tf((c & 1) ? t1 : t0);
            uint32_t a1 = f2tf((c & 1) ? t3 : t2);
            uint32_t a2 = f2tf((c & 1) ? u1 : u0);
            uint32_t a3 = f2tf((c & 1) ? u3 : u2);
#pragma unroll
            for (int nb = 0; nb < 8; nb++) {
                uint32_t b0 = __float_as_uint(Vs[ks*8 + c][nb*8 + q]);
                uint32_t b1 = __float_as_uint(Vs[ks*8 + c + 4][nb*8 + q]);
                mma_tf32(o[nb][0], o[nb][1], o[nb][2], o[nb][3],
                         a0, a1, a2, a3, b0, b1);
            }
        }
    }
    float inv_a = 1.f/l_a, inv_b = 1.f/l_b;
    size_t oba = ((size_t)(b*SS + ra))*DD + h*64;
    size_t obb = ((size_t)(b*SS + rb))*DD + h*64;
#pragma unroll
    for (int nb = 0; nb < 8; nb++) {
        *(float2*)(g_ybuf + oba + nb*8 + 2*c) = make_float2(o[nb][0]*inv_a, o[nb][1]*inv_a);
        *(float2*)(g_ybuf + obb + nb*8 + 2*c) = make_float2(o[nb][2]*inv_b, o[nb][3]*inv_b);
    }
}

// ---------------- zero expert counters ----------------
__global__ void k_zero() { if (threadIdx.x < NE) g_cnt[threadIdx.x] = 0; }

// ---------------- velocity + second rmsnorm + expert bucketing ----------------
__global__ void k_vel(const float* __restrict__ vel, const float* __restrict__ mu,
                      const int* __restrict__ eids, float* __restrict__ out) {
    int t = blockIdx.x, tid = threadIdx.x;
    float xv[4]; float ss = 0.f;
#pragma unroll
    for (int r = 0; r < 4; r++) {
        int d = tid + r*256;
        size_t idx = (size_t)t*DD + d;
        float x2 = g_x2[idx];
        float mc = fminf(fmaxf(mu[d], 0.5f), 1.5f);
        float v = fminf(fmaxf(0.95f*vel[idx] - 0.3f*(x2 - mc), -3.f), 3.f);
        out[(size_t)NTOK*DD + idx] = v;
        float x3 = x2 + 0.01f*v;
        xv[r] = x3; ss += x3*x3;
        g_x3[idx] = x3;
    }
    __shared__ float red[32];
#pragma unroll
    for (int o = 16; o > 0; o >>= 1) ss += __shfl_xor_sync(0xffffffffu, ss, o);
    if ((tid & 31) == 0) red[tid >> 5] = ss;
    __syncthreads();
    if (tid < 32) {
        float s2 = (tid < 8) ? red[tid] : 0.f;
#pragma unroll
        for (int o = 4; o > 0; o >>= 1) s2 += __shfl_xor_sync(0xffffffffu, s2, o);
        if (tid == 0) red[0] = s2;
    }
    __syncthreads();
    float rms = rsqrtf(red[0]/(float)DD + EPSF);
#pragma unroll
    for (int r = 0; r < 4; r++) {
        int d = tid + r*256;
        g_mbuf[(size_t)t*DD + d] = xv[r]*rms;
    }
    if (tid == 0) {
        int e = eids[t];
        int p = atomicAdd(&g_cnt[e], 1);
        g_tok[e*NTOK + p] = t;
    }
}

// ---------------- silu(g)*u ----------------
__global__ void k_silu() {
    int idx = blockIdx.x*256 + threadIdx.x;
    int t = idx >> 9, i = idx & 511;
    float g = g_gu[(size_t)t*1024 + i];
    float u = g_gu[(size_t)t*1024 + 512 + i];
    g_hbuf[(size_t)t*512 + i] = g/(1.f + __expf(-g))*u;
}

// ---------------- launch ----------------
extern "C" void kernel_launch(void* const* d_in, const int* in_sizes, int n_in,
                              void* d_out, int out_size) {
    const float* x        = (const float*)d_in[0];
    const float* x0       = (const float*)d_in[1];
    const float* vel      = (const float*)d_in[2];
    const float* resid    = (const float*)d_in[3];
    const float* attn_sc  = (const float*)d_in[4];
    const float* mlp_sc   = (const float*)d_in[5];
    const float* cq_w     = (const float*)d_in[6];
    const float* ck_w     = (const float*)d_in[7];
    const float* cv_w     = (const float*)d_in[8];
    const float* proj_w   = (const float*)d_in[9];
    const float* q_gain   = (const float*)d_in[10];
    const float* mu       = (const float*)d_in[11];
    const float* gate_up  = (const float*)d_in[12];
    const float* down     = (const float*)d_in[13];
    const int*   eids     = (const int*)d_in[14];
    float* out = (float*)d_out;

    float *p_nbuf, *p_qlin, *p_klin, *p_vlin, *p_ybuf, *p_x2, *p_gu, *p_h, *p_m, *p_xbuf;
    cudaGetSymbolAddress((void**)&p_nbuf, g_nbuf);
    cudaGetSymbolAddress((void**)&p_qlin, g_qlin);
    cudaGetSymbolAddress((void**)&p_klin, g_klin);
    cudaGetSymbolAddress((void**)&p_vlin, g_vlin);
    cudaGetSymbolAddress((void**)&p_ybuf, g_ybuf);
    cudaGetSymbolAddress((void**)&p_x2,   g_x2);
    cudaGetSymbolAddress((void**)&p_gu,   g_gu);
    cudaGetSymbolAddress((void**)&p_h,    g_hbuf);
    cudaGetSymbolAddress((void**)&p_m,    g_mbuf);
    cudaGetSymbolAddress((void**)&p_xbuf, g_xbuf);

    k_mix_norm<<<NTOK, 256>>>(x, x0, resid);

    gemm_mma_tn<0><<<dim3(DD/128, NTOK/128, 1), 256>>>(p_nbuf, cq_w, nullptr,
                                                       p_qlin, nullptr, DD, DD,
                                                       nullptr, nullptr);
    gemm_mma_tn<0><<<dim3(KVD/128, NTOK/128, 2), 256>>>(p_nbuf, ck_w, cv_w,
                                                        p_klin, p_vlin, KVD, DD,
                                                        nullptr, nullptr);

    k_hnr<<<dim3(NTOK, 3), 256>>>(q_gain);

    k_flash_mma<<<dim3(SS/128, BB*NH), 256>>>();

    gemm_mma_tn<1><<<dim3(DD/128, NTOK/128, 1), 256>>>(p_ybuf, proj_w, nullptr,
                                                       p_x2, nullptr, DD, DD,
                                                       p_xbuf, attn_sc);

    k_zero<<<1, 32>>>();
    k_vel<<<NTOK, 256>>>(vel, mu, eids, out);

    gemm_mma_nn<0><<<dim3(1024/128, NTOK/128, NE), 256>>>(p_m, gate_up, 1024, DD,
                                                          p_gu, nullptr, nullptr);
    k_silu<<<(NTOK*INTER)/256, 256>>>();
    gemm_mma_nn<1><<<dim3(DD/128, NTOK/128, NE), 256>>>(p_h, down, DD, INTER,
                                                        nullptr, mlp_sc, out);
}